// round 6
// baseline (speedup 1.0000x reference)
#include <cuda_runtime.h>

// Problem dims (fixed): inputs [4,2048,2048] f32, W1/W2 [2048,2048] f32.
#define MTOT 8192
#define NTOT 2048
#define KTOT 2048
#define NELEM 16777216u  // 4*2048*2048 = 2^24

// Scratch (static device globals; no allocation allowed in kernel_launch).
__device__ float g_xnorm[(size_t)MTOT * NTOT];   // 64 MiB
__device__ float g_h[(size_t)MTOT * NTOT];       // 64 MiB
__device__ unsigned char g_mask[(size_t)MTOT * NTOT]; // 16 MiB

// ---------------- packed f32x2 helpers (Blackwell PTX) ----------------
__device__ __forceinline__ unsigned long long dup2(float x) {
    unsigned long long r;
    asm("mov.b64 %0, {%1,%1};" : "=l"(r) : "f"(x));
    return r;
}
__device__ __forceinline__ void fma2(unsigned long long& d, unsigned long long a,
                                     unsigned long long b) {
    asm("fma.rn.f32x2 %0, %1, %2, %0;" : "+l"(d) : "l"(a), "l"(b));
}
__device__ __forceinline__ float2 unpack2(unsigned long long v) {
    float2 f;
    asm("mov.b64 {%0,%1}, %2;" : "=f"(f.x), "=f"(f.y) : "l"(v));
    return f;
}

// ---------------- LayerNorm: one block per row ----------------
__global__ void __launch_bounds__(256) ln_kernel(const float* __restrict__ in) {
    const int row = blockIdx.x;
    const int t = threadIdx.x;
    const float4* ip = (const float4*)(in + (size_t)row * NTOT);
    float4* op = (float4*)(g_xnorm + (size_t)row * NTOT);

    float4 v0 = ip[t];
    float4 v1 = ip[t + 256];
    float s = v0.x + v0.y + v0.z + v0.w + v1.x + v1.y + v1.z + v1.w;
    float q = v0.x * v0.x + v0.y * v0.y + v0.z * v0.z + v0.w * v0.w +
              v1.x * v1.x + v1.y * v1.y + v1.z * v1.z + v1.w * v1.w;

#pragma unroll
    for (int o = 16; o > 0; o >>= 1) {
        s += __shfl_xor_sync(0xffffffffu, s, o);
        q += __shfl_xor_sync(0xffffffffu, q, o);
    }
    __shared__ float rs[8], rq[8];
    if ((t & 31) == 0) { rs[t >> 5] = s; rq[t >> 5] = q; }
    __syncthreads();
    if (t < 8) {
        s = rs[t]; q = rq[t];
#pragma unroll
        for (int o = 4; o > 0; o >>= 1) {
            s += __shfl_xor_sync(0xffu, s, o);
            q += __shfl_xor_sync(0xffu, q, o);
        }
        if (t == 0) { rs[0] = s; rq[0] = q; }
    }
    __syncthreads();

    const float mean = rs[0] * (1.0f / (float)NTOT);
    const float var = rq[0] * (1.0f / (float)NTOT) - mean * mean;
    const float rstd = rsqrtf(var + 1e-6f);

    v0.x = (v0.x - mean) * rstd; v0.y = (v0.y - mean) * rstd;
    v0.z = (v0.z - mean) * rstd; v0.w = (v0.w - mean) * rstd;
    v1.x = (v1.x - mean) * rstd; v1.y = (v1.y - mean) * rstd;
    v1.z = (v1.z - mean) * rstd; v1.w = (v1.w - mean) * rstd;
    op[t] = v0;
    op[t + 256] = v1;
}

// ---------------- Dropout mask: JAX threefry2x32, PARTITIONABLE path ----------------
// jax_threefry_partitionable=True (default since JAX 0.4.30):
// per-element 64-bit counter i -> (hi = i>>32 = 0 here, lo = i);
// threefry2x32(key=(0,1), x0=hi, x1=lo); 32-bit output = out0 ^ out1.
#define TFR(r)                                   \
    do {                                         \
        x0 += x1;                                \
        x1 = __funnelshift_l(x1, x1, (r));       \
        x1 ^= x0;                                \
    } while (0)

__global__ void __launch_bounds__(256) mask_kernel() {
    const unsigned int i = blockIdx.x * 256u + threadIdx.x;  // < 2^24
    unsigned int x0 = 0u;   // counts_hi (i < 2^32)
    unsigned int x1 = i;    // counts_lo
    const unsigned int ks0 = 0u, ks1 = 1u, ks2 = 0x1BD11BDBu;  // 0x1BD11BDA ^ 0 ^ 1

    x0 += ks0; x1 += ks1;
    TFR(13); TFR(15); TFR(26); TFR(6);
    x0 += ks1; x1 += ks2 + 1u;
    TFR(17); TFR(29); TFR(16); TFR(24);
    x0 += ks2; x1 += ks0 + 2u;
    TFR(13); TFR(15); TFR(26); TFR(6);
    x0 += ks0; x1 += ks1 + 3u;
    TFR(17); TFR(29); TFR(16); TFR(24);
    x0 += ks1; x1 += ks2 + 4u;
    TFR(13); TFR(15); TFR(26); TFR(6);
    x0 += ks2; x1 += ks0 + 5u;

    const unsigned int bits = x0 ^ x1;
    const float u = __uint_as_float((bits >> 9) | 0x3f800000u) - 1.0f;
    g_mask[i] = (u < 0.75f) ? 1 : 0;
}

// ---------------- SGEMM: 128x128x8 tile, 256 thr, 8x8 microtile, f32x2 FMA ----------------
// PHASE 0: g_h = relu(g_xnorm @ W1)
// PHASE 1: out  = g_xnorm + dropout(g_h @ W2)
template <int PHASE>
__global__ void __launch_bounds__(256, 2) sgemm_kernel(const float* __restrict__ Bw,
                                                       float* __restrict__ Cext) {
    __shared__ float As[2][8][132];  // [k][m], padded to kill store conflicts
    __shared__ float Bs[2][8][128];  // [k][n]

    const float* Aptr = (PHASE == 0) ? g_xnorm : g_h;
    float* Cptr = (PHASE == 0) ? g_h : Cext;

    const int tid = threadIdx.x;
    const int bx = blockIdx.x;  // N tile (16)
    const int by = blockIdx.y;  // M tile (64)
    const int tx8 = (tid & 15) * 8;
    const int ty8 = (tid >> 4) * 8;

    // global load mapping: A tile 128x8 -> 256 float4; B tile 8x128 -> 256 float4
    const int a_row = tid >> 1;
    const int a_col = (tid & 1) << 2;
    const int b_row = tid >> 5;
    const int b_col = (tid & 31) << 2;

    const float* Ag = Aptr + (size_t)(by * 128 + a_row) * KTOT + a_col;
    const float* Bg = Bw + (size_t)b_row * NTOT + bx * 128 + b_col;

    // preload tile 0
    {
        float4 av = *(const float4*)Ag;
        float4 bv = *(const float4*)Bg;
        As[0][a_col + 0][a_row] = av.x;
        As[0][a_col + 1][a_row] = av.y;
        As[0][a_col + 2][a_row] = av.z;
        As[0][a_col + 3][a_row] = av.w;
        *(float4*)&Bs[0][b_row][b_col] = bv;
    }
    __syncthreads();

    unsigned long long acc[8][4];
#pragma unroll
    for (int i = 0; i < 8; i++)
#pragma unroll
        for (int j = 0; j < 4; j++) acc[i][j] = 0ull;

    int buf = 0;
#pragma unroll 1
    for (int kt = 0; kt < KTOT; kt += 8) {
        const bool has_next = (kt + 8) < KTOT;
        float4 av_n, bv_n;
        if (has_next) {
            av_n = *(const float4*)(Ag + (kt + 8));
            bv_n = *(const float4*)(Bg + (size_t)(kt + 8) * NTOT);
        }

        // compute current tile
#pragma unroll
        for (int k = 0; k < 8; k++) {
            const float4 a0 = *(const float4*)&As[buf][k][ty8];
            const float4 a1 = *(const float4*)&As[buf][k][ty8 + 4];
            const unsigned long long* bp = (const unsigned long long*)&Bs[buf][k][tx8];
            const unsigned long long b0 = bp[0], b1 = bp[1], b2v = bp[2], b3 = bp[3];
            const float af[8] = {a0.x, a0.y, a0.z, a0.w, a1.x, a1.y, a1.z, a1.w};
#pragma unroll
            for (int i = 0; i < 8; i++) {
                const unsigned long long a2 = dup2(af[i]);
                fma2(acc[i][0], a2, b0);
                fma2(acc[i][1], a2, b1);
                fma2(acc[i][2], a2, b2v);
                fma2(acc[i][3], a2, b3);
            }
        }

        if (has_next) {
            const int nb = buf ^ 1;
            As[nb][a_col + 0][a_row] = av_n.x;
            As[nb][a_col + 1][a_row] = av_n.y;
            As[nb][a_col + 2][a_row] = av_n.z;
            As[nb][a_col + 3][a_row] = av_n.w;
            *(float4*)&Bs[nb][b_row][b_col] = bv_n;
            __syncthreads();
            buf = nb;
        }
    }

    // epilogue
    const int row0 = by * 128 + ty8;
    const int col0 = bx * 128 + tx8;
#pragma unroll
    for (int i = 0; i < 8; i++) {
        const float2 p0 = unpack2(acc[i][0]);
        const float2 p1 = unpack2(acc[i][1]);
        const float2 p2 = unpack2(acc[i][2]);
        const float2 p3 = unpack2(acc[i][3]);
        const size_t base = (size_t)(row0 + i) * NTOT + col0;
        if (PHASE == 0) {
            float4 o0 = make_float4(fmaxf(p0.x, 0.0f), fmaxf(p0.y, 0.0f),
                                    fmaxf(p1.x, 0.0f), fmaxf(p1.y, 0.0f));
            float4 o1 = make_float4(fmaxf(p2.x, 0.0f), fmaxf(p2.y, 0.0f),
                                    fmaxf(p3.x, 0.0f), fmaxf(p3.y, 0.0f));
            *(float4*)(Cptr + base) = o0;
            *(float4*)(Cptr + base + 4) = o1;
        } else {
            const unsigned long long mb = *(const unsigned long long*)(g_mask + base);
            const float4 r0 = *(const float4*)(g_xnorm + base);
            const float4 r1 = *(const float4*)(g_xnorm + base + 4);
            const float sc = 1.0f / 0.75f;
            float v[8] = {p0.x, p0.y, p1.x, p1.y, p2.x, p2.y, p3.x, p3.y};
            float o[8];
#pragma unroll
            for (int j = 0; j < 8; j++) {
                const bool keep = ((mb >> (8 * j)) & 0xffull) != 0ull;
                o[j] = keep ? v[j] * sc : 0.0f;
            }
            float4 w0 = make_float4(r0.x + o[0], r0.y + o[1], r0.z + o[2], r0.w + o[3]);
            float4 w1 = make_float4(r1.x + o[4], r1.y + o[5], r1.z + o[6], r1.w + o[7]);
            *(float4*)(Cptr + base) = w0;
            *(float4*)(Cptr + base + 4) = w1;
        }
    }
}

extern "C" void kernel_launch(void* const* d_in, const int* in_sizes, int n_in,
                              void* d_out, int out_size) {
    const float* inputs = (const float*)d_in[0];
    const float* W1 = (const float*)d_in[1];
    const float* W2 = (const float*)d_in[2];
    float* out = (float*)d_out;
    (void)in_sizes; (void)n_in; (void)out_size;

    ln_kernel<<<MTOT, 256>>>(inputs);
    mask_kernel<<<NELEM / 256, 256>>>();

    dim3 grid(NTOT / 128, MTOT / 128);
    sgemm_kernel<0><<<grid, 256>>>(W1, nullptr);
    sgemm_kernel<1><<<grid, 256>>>(W2, out);
}

// round 8
// speedup vs baseline: 3.4181x; 3.4181x over previous
#include <cuda_runtime.h>
#include <cuda_fp16.h>
#include <cstdint>

// Problem dims (fixed): inputs [4,2048,2048] f32, W1/W2 [2048,2048] f32.
#define MTOT 8192
#define NTOT 2048
#define KTOT 2048
#define NELEM 16777216u  // 2^24

// ---------------- scratch globals (no allocation allowed) ----------------
__device__ __align__(256) float g_xnorm[(size_t)MTOT * NTOT];   // 64 MiB (residual, fp32)
__device__ __align__(256) __half g_xn_h[(size_t)MTOT * NTOT];   // 32 MiB
__device__ __align__(256) __half g_h_h[(size_t)MTOT * NTOT];    // 32 MiB
__device__ __align__(256) __half g_w1t[(size_t)NTOT * KTOT];    // 8 MiB, transposed [n][k]
__device__ __align__(256) __half g_w2t[(size_t)NTOT * KTOT];    // 8 MiB
__device__ __align__(256) unsigned char g_mask[(size_t)MTOT * NTOT];  // 16 MiB

// ---------------- helpers ----------------
__device__ __forceinline__ uint32_t smem_u32(const void* p) {
    uint32_t a;
    asm("{ .reg .u64 t; cvta.to.shared.u64 t, %1; cvt.u32.u64 %0, t; }" : "=r"(a) : "l"(p));
    return a;
}
__device__ __forceinline__ void cp16(uint32_t s, const void* g) {
    asm volatile("cp.async.cg.shared.global [%0], [%1], 16;" ::"r"(s), "l"(g));
}
__device__ __forceinline__ void mma16816(float* c, const uint32_t* a, uint32_t b0,
                                         uint32_t b1) {
    asm volatile(
        "mma.sync.aligned.m16n8k16.row.col.f32.f16.f16.f32 "
        "{%0,%1,%2,%3},{%4,%5,%6,%7},{%8,%9},{%0,%1,%2,%3};"
        : "+f"(c[0]), "+f"(c[1]), "+f"(c[2]), "+f"(c[3])
        : "r"(a[0]), "r"(a[1]), "r"(a[2]), "r"(a[3]), "r"(b0), "r"(b1));
}
__device__ __forceinline__ uint32_t pack_h2(float a, float b) {
    __half2 h = __floats2half2_rn(a, b);
    return *(uint32_t*)&h;
}

// ---------------- LayerNorm: one block per row; emits fp32 + fp16 ----------------
__global__ void __launch_bounds__(256) ln_kernel(const float* __restrict__ in) {
    const int row = blockIdx.x;
    const int t = threadIdx.x;
    const float4* ip = (const float4*)(in + (size_t)row * NTOT);
    float4* op = (float4*)(g_xnorm + (size_t)row * NTOT);

    float4 v0 = ip[t];
    float4 v1 = ip[t + 256];
    float s = v0.x + v0.y + v0.z + v0.w + v1.x + v1.y + v1.z + v1.w;
    float q = v0.x * v0.x + v0.y * v0.y + v0.z * v0.z + v0.w * v0.w +
              v1.x * v1.x + v1.y * v1.y + v1.z * v1.z + v1.w * v1.w;

#pragma unroll
    for (int o = 16; o > 0; o >>= 1) {
        s += __shfl_xor_sync(0xffffffffu, s, o);
        q += __shfl_xor_sync(0xffffffffu, q, o);
    }
    __shared__ float rs[8], rq[8];
    if ((t & 31) == 0) { rs[t >> 5] = s; rq[t >> 5] = q; }
    __syncthreads();
    if (t < 8) {
        s = rs[t]; q = rq[t];
#pragma unroll
        for (int o = 4; o > 0; o >>= 1) {
            s += __shfl_xor_sync(0xffu, s, o);
            q += __shfl_xor_sync(0xffu, q, o);
        }
        if (t == 0) { rs[0] = s; rq[0] = q; }
    }
    __syncthreads();

    const float mean = rs[0] * (1.0f / (float)NTOT);
    const float var = rq[0] * (1.0f / (float)NTOT) - mean * mean;
    const float rstd = rsqrtf(var + 1e-6f);

    v0.x = (v0.x - mean) * rstd; v0.y = (v0.y - mean) * rstd;
    v0.z = (v0.z - mean) * rstd; v0.w = (v0.w - mean) * rstd;
    v1.x = (v1.x - mean) * rstd; v1.y = (v1.y - mean) * rstd;
    v1.z = (v1.z - mean) * rstd; v1.w = (v1.w - mean) * rstd;
    op[t] = v0;
    op[t + 256] = v1;

    uint2* hp = (uint2*)(g_xn_h + (size_t)row * NTOT);
    uint2 h0, h1;
    h0.x = pack_h2(v0.x, v0.y); h0.y = pack_h2(v0.z, v0.w);
    h1.x = pack_h2(v1.x, v1.y); h1.y = pack_h2(v1.z, v1.w);
    hp[t] = h0;
    hp[t + 256] = h1;
}

// ---------------- W prep: transpose + fp16. W[k][n] -> Wt[n][k] ----------------
template <int WHICH>
__global__ void __launch_bounds__(256) prep_w(const float* __restrict__ W) {
    __half* Wt = (WHICH == 0) ? g_w1t : g_w2t;
    __shared__ float tile[32][33];
    const int bx = blockIdx.x * 32;  // n block
    const int by = blockIdx.y * 32;  // k block
    const int tx = threadIdx.x & 31;
    const int ty = threadIdx.x >> 5;  // 0..7
#pragma unroll
    for (int j = 0; j < 32; j += 8)
        tile[ty + j][tx] = W[(size_t)(by + ty + j) * NTOT + bx + tx];
    __syncthreads();
#pragma unroll
    for (int j = 0; j < 32; j += 8) {
        const int n = bx + ty + j, k = by + tx;
        Wt[(size_t)n * KTOT + k] = __float2half_rn(tile[tx][ty + j]);
    }
}

// ---------------- Dropout mask: JAX threefry2x32 partitionable (verified R6) ----------------
#define TFR(r)                             \
    do {                                   \
        x0 += x1;                          \
        x1 = __funnelshift_l(x1, x1, (r)); \
        x1 ^= x0;                          \
    } while (0)

__global__ void __launch_bounds__(256) mask_kernel() {
    const unsigned int i = blockIdx.x * 256u + threadIdx.x;
    unsigned int x0 = 0u;
    unsigned int x1 = i;
    const unsigned int ks0 = 0u, ks1 = 1u, ks2 = 0x1BD11BDBu;

    x0 += ks0; x1 += ks1;
    TFR(13); TFR(15); TFR(26); TFR(6);
    x0 += ks1; x1 += ks2 + 1u;
    TFR(17); TFR(29); TFR(16); TFR(24);
    x0 += ks2; x1 += ks0 + 2u;
    TFR(13); TFR(15); TFR(26); TFR(6);
    x0 += ks0; x1 += ks1 + 3u;
    TFR(17); TFR(29); TFR(16); TFR(24);
    x0 += ks1; x1 += ks2 + 4u;
    TFR(13); TFR(15); TFR(26); TFR(6);
    x0 += ks2; x1 += ks0 + 5u;

    const unsigned int bits = x0 ^ x1;
    const float u = __uint_as_float((bits >> 9) | 0x3f800000u) - 1.0f;
    g_mask[i] = (u < 0.75f) ? 1 : 0;
}

// ---------------- HMMA GEMM (base-ISA mma.sync; tcgen05 is blocked by toolchain) -----
// CTA 128x256, 8 warps (2M x 4N), warp tile 64x64, K-chunk 32, 3-stage cp.async.
// Smem per stage: A 128 rows x 80B pitch (32 halves + pad) = 10240; B 256 x 80 = 20480.
// PHASE 0: g_h_h = fp16(relu(xn @ W1));  PHASE 1: out = xnorm + dropout(h @ W2).
#define APITCH 80
#define SM_B_OFF 10240
#define STAGE_BYTES 30720
#define GEMM_SMEM (3 * STAGE_BYTES)

template <int PHASE>
__global__ void __launch_bounds__(256, 1) gemm_mma(float* __restrict__ Cext) {
    extern __shared__ __align__(128) char smem[];
    const uint32_t sb = smem_u32(smem);
    const int tid = threadIdx.x;

    const __half* __restrict__ Ag = (PHASE == 0) ? g_xn_h : g_h_h;
    const __half* __restrict__ Bg = (PHASE == 0) ? g_w1t : g_w2t;
    const int m0 = blockIdx.y * 128;
    const int n0 = blockIdx.x * 256;

    // Loader mapping. A: 512 16B-vecs (thread -> row tid/2, vecs {0,1}+2*(tid&1)).
    // B: 1024 vecs (thread -> row tid, vecs 0..3). All K-contiguous.
    const int ar = tid >> 1, av = (tid & 1) * 2;
    const __half* agp = Ag + (size_t)(m0 + ar) * KTOT + av * 8;
    const uint32_t a_soff = (uint32_t)(ar * APITCH + av * 16);
    const __half* bgp = Bg + (size_t)(n0 + tid) * KTOT;
    const uint32_t b_soff = (uint32_t)(SM_B_OFF + tid * APITCH);

#define LOAD_STAGE(sidx, kc)                                    \
    do {                                                        \
        const uint32_t _st = sb + (sidx) * STAGE_BYTES;         \
        cp16(_st + a_soff, agp + (kc));                         \
        cp16(_st + a_soff + 16, agp + (kc) + 8);                \
        cp16(_st + b_soff, bgp + (kc));                         \
        cp16(_st + b_soff + 16, bgp + (kc) + 8);                \
        cp16(_st + b_soff + 32, bgp + (kc) + 16);               \
        cp16(_st + b_soff + 48, bgp + (kc) + 24);               \
    } while (0)

    LOAD_STAGE(0, 0);
    asm volatile("cp.async.commit_group;" ::: "memory");
    LOAD_STAGE(1, 32);
    asm volatile("cp.async.commit_group;" ::: "memory");

    const int lane = tid & 31;
    const int wid = tid >> 5;
    const int wm = (wid >> 2) * 64;  // 0,64
    const int wn = (wid & 3) * 64;   // 0..192

    float acc[4][8][4];
#pragma unroll
    for (int mt = 0; mt < 4; mt++)
#pragma unroll
        for (int nt = 0; nt < 8; nt++)
#pragma unroll
            for (int j = 0; j < 4; j++) acc[mt][nt][j] = 0.0f;

    // Fragment bases (byte offsets within a stage).
    const uint32_t a_lm = (uint32_t)((wm + (lane & 15)) * APITCH + ((lane >> 4) * 8) * 2);
    const uint32_t b_ld = (uint32_t)(SM_B_OFF + (wn + (lane >> 2)) * APITCH + ((lane & 3) * 2) * 2);

#pragma unroll 1
    for (int c = 0; c < KTOT / 32; c++) {
        asm volatile("cp.async.wait_group 1;" ::: "memory");
        __syncthreads();
        if (c + 2 < KTOT / 32) {
            const int s2 = (c + 2) % 3;
            const int kc = (c + 2) * 32;
            LOAD_STAGE(s2, kc);
        }
        asm volatile("cp.async.commit_group;" ::: "memory");

        const uint32_t st = sb + (c % 3) * STAGE_BYTES;
        const char* stp = smem + (c % 3) * STAGE_BYTES;
#pragma unroll
        for (int h = 0; h < 2; h++) {
            const uint32_t k0b = h * 32;  // 16 halves * 2B
            uint32_t a[4][4];
#pragma unroll
            for (int mt = 0; mt < 4; mt++) {
                const uint32_t addr = st + a_lm + mt * 16 * APITCH + k0b;
                asm volatile(
                    "ldmatrix.sync.aligned.m8n8.x4.shared.b16 {%0,%1,%2,%3},[%4];"
                    : "=r"(a[mt][0]), "=r"(a[mt][1]), "=r"(a[mt][2]), "=r"(a[mt][3])
                    : "r"(addr));
            }
#pragma unroll
            for (int nt = 0; nt < 8; nt++) {
                const char* bp = stp + (b_ld - SM_B_OFF) + SM_B_OFF + nt * 8 * APITCH + k0b;
                const uint32_t b0 = *(const uint32_t*)bp;
                const uint32_t b1 = *(const uint32_t*)(bp + 16);
#pragma unroll
                for (int mt = 0; mt < 4; mt++) mma16816(acc[mt][nt], a[mt], b0, b1);
            }
        }
    }

    // ---------------- epilogue ----------------
    const int rbase = m0 + wm + (lane >> 2);
    const int cbase = n0 + wn + (lane & 3) * 2;
    const float sc = 1.0f / 0.75f;
#pragma unroll
    for (int mt = 0; mt < 4; mt++) {
#pragma unroll
        for (int half = 0; half < 2; half++) {
            const int row = rbase + mt * 16 + half * 8;
            const size_t rowb = (size_t)row * NTOT;
#pragma unroll
            for (int nt = 0; nt < 8; nt++) {
                const int col = cbase + nt * 8;
                const float v0 = acc[mt][nt][2 * half];
                const float v1 = acc[mt][nt][2 * half + 1];
                if (PHASE == 0) {
                    *(uint32_t*)(g_h_h + rowb + col) =
                        pack_h2(fmaxf(v0, 0.0f), fmaxf(v1, 0.0f));
                } else {
                    const uint16_t mk = *(const uint16_t*)(g_mask + rowb + col);
                    const float2 xr = *(const float2*)(g_xnorm + rowb + col);
                    float2 o;
                    o.x = xr.x + ((mk & 0xffu) ? v0 * sc : 0.0f);
                    o.y = xr.y + ((mk >> 8) ? v1 * sc : 0.0f);
                    *(float2*)(Cext + rowb + col) = o;
                }
            }
        }
    }
#undef LOAD_STAGE
}

extern "C" void kernel_launch(void* const* d_in, const int* in_sizes, int n_in,
                              void* d_out, int out_size) {
    const float* inputs = (const float*)d_in[0];
    const float* W1 = (const float*)d_in[1];
    const float* W2 = (const float*)d_in[2];
    float* out = (float*)d_out;
    (void)in_sizes; (void)n_in; (void)out_size;

    cudaFuncSetAttribute(gemm_mma<0>, cudaFuncAttributeMaxDynamicSharedMemorySize, GEMM_SMEM);
    cudaFuncSetAttribute(gemm_mma<1>, cudaFuncAttributeMaxDynamicSharedMemorySize, GEMM_SMEM);

    dim3 tgrid(64, 64);
    prep_w<0><<<tgrid, 256>>>(W1);
    prep_w<1><<<tgrid, 256>>>(W2);
    ln_kernel<<<MTOT, 256>>>(inputs);
    mask_kernel<<<NELEM / 256, 256>>>();

    dim3 grid(NTOT / 256, MTOT / 128);
    gemm_mma<0><<<grid, 256, GEMM_SMEM>>>(nullptr);
    gemm_mma<1><<<grid, 256, GEMM_SMEM>>>(out);
}

// round 9
// speedup vs baseline: 4.9168x; 1.4385x over previous
#include <cuda_runtime.h>
#include <cuda_fp16.h>
#include <cstdint>

// Problem dims (fixed): inputs [4,2048,2048] f32, W1/W2 [2048,2048] f32.
#define MTOT 8192
#define NTOT 2048
#define KTOT 2048

// ---------------- scratch globals (no allocation allowed) ----------------
__device__ __align__(256) float g_xnorm[(size_t)MTOT * NTOT];   // 64 MiB (residual, fp32)
__device__ __align__(256) __half g_xn_h[(size_t)MTOT * NTOT];   // 32 MiB
__device__ __align__(256) __half g_h_h[(size_t)MTOT * NTOT];    // 32 MiB
__device__ __align__(256) __half g_w1t[(size_t)NTOT * KTOT];    // 8 MiB, transposed [n][k]
__device__ __align__(256) __half g_w2t[(size_t)NTOT * KTOT];    // 8 MiB

// ---------------- helpers ----------------
__device__ __forceinline__ uint32_t smem_u32(const void* p) {
    uint32_t a;
    asm("{ .reg .u64 t; cvta.to.shared.u64 t, %1; cvt.u32.u64 %0, t; }" : "=r"(a) : "l"(p));
    return a;
}
__device__ __forceinline__ void cp16(uint32_t s, const void* g) {
    asm volatile("cp.async.cg.shared.global [%0], [%1], 16;" ::"r"(s), "l"(g));
}
__device__ __forceinline__ void mma16816(float* c, const uint32_t* a, uint32_t b0,
                                         uint32_t b1) {
    asm volatile(
        "mma.sync.aligned.m16n8k16.row.col.f32.f16.f16.f32 "
        "{%0,%1,%2,%3},{%4,%5,%6,%7},{%8,%9},{%0,%1,%2,%3};"
        : "+f"(c[0]), "+f"(c[1]), "+f"(c[2]), "+f"(c[3])
        : "r"(a[0]), "r"(a[1]), "r"(a[2]), "r"(a[3]), "r"(b0), "r"(b1));
}
__device__ __forceinline__ uint32_t pack_h2(float a, float b) {
    __half2 h = __floats2half2_rn(a, b);
    return *(uint32_t*)&h;
}

// ---------------- JAX threefry2x32 keep-decision (partitionable path, verified R6) ----
#define TFR(r)                             \
    do {                                   \
        x0 += x1;                          \
        x1 = __funnelshift_l(x1, x1, (r)); \
        x1 ^= x0;                          \
    } while (0)
__device__ __forceinline__ bool tf_keep(uint32_t i) {
    uint32_t x0 = 0u, x1 = i;
    const uint32_t ks0 = 0u, ks1 = 1u, ks2 = 0x1BD11BDBu;
    x0 += ks0; x1 += ks1;
    TFR(13); TFR(15); TFR(26); TFR(6);
    x0 += ks1; x1 += ks2 + 1u;
    TFR(17); TFR(29); TFR(16); TFR(24);
    x0 += ks2; x1 += ks0 + 2u;
    TFR(13); TFR(15); TFR(26); TFR(6);
    x0 += ks0; x1 += ks1 + 3u;
    TFR(17); TFR(29); TFR(16); TFR(24);
    x0 += ks1; x1 += ks2 + 4u;
    TFR(13); TFR(15); TFR(26); TFR(6);
    x0 += ks2; x1 += ks0 + 5u;
    const uint32_t bits = x0 ^ x1;
    const float u = __uint_as_float((bits >> 9) | 0x3f800000u) - 1.0f;
    return u < 0.75f;
}

// ---------------- LayerNorm: one block per row; emits fp32 + fp16 ----------------
__global__ void __launch_bounds__(256) ln_kernel(const float* __restrict__ in) {
    const int row = blockIdx.x;
    const int t = threadIdx.x;
    const float4* ip = (const float4*)(in + (size_t)row * NTOT);
    float4* op = (float4*)(g_xnorm + (size_t)row * NTOT);

    float4 v0 = ip[t];
    float4 v1 = ip[t + 256];
    float s = v0.x + v0.y + v0.z + v0.w + v1.x + v1.y + v1.z + v1.w;
    float q = v0.x * v0.x + v0.y * v0.y + v0.z * v0.z + v0.w * v0.w +
              v1.x * v1.x + v1.y * v1.y + v1.z * v1.z + v1.w * v1.w;

#pragma unroll
    for (int o = 16; o > 0; o >>= 1) {
        s += __shfl_xor_sync(0xffffffffu, s, o);
        q += __shfl_xor_sync(0xffffffffu, q, o);
    }
    __shared__ float rs[8], rq[8];
    if ((t & 31) == 0) { rs[t >> 5] = s; rq[t >> 5] = q; }
    __syncthreads();
    if (t < 8) {
        s = rs[t]; q = rq[t];
#pragma unroll
        for (int o = 4; o > 0; o >>= 1) {
            s += __shfl_xor_sync(0xffu, s, o);
            q += __shfl_xor_sync(0xffu, q, o);
        }
        if (t == 0) { rs[0] = s; rq[0] = q; }
    }
    __syncthreads();

    const float mean = rs[0] * (1.0f / (float)NTOT);
    const float var = rq[0] * (1.0f / (float)NTOT) - mean * mean;
    const float rstd = rsqrtf(var + 1e-6f);

    v0.x = (v0.x - mean) * rstd; v0.y = (v0.y - mean) * rstd;
    v0.z = (v0.z - mean) * rstd; v0.w = (v0.w - mean) * rstd;
    v1.x = (v1.x - mean) * rstd; v1.y = (v1.y - mean) * rstd;
    v1.z = (v1.z - mean) * rstd; v1.w = (v1.w - mean) * rstd;
    op[t] = v0;
    op[t + 256] = v1;

    uint2* hp = (uint2*)(g_xn_h + (size_t)row * NTOT);
    uint2 h0, h1;
    h0.x = pack_h2(v0.x, v0.y); h0.y = pack_h2(v0.z, v0.w);
    h1.x = pack_h2(v1.x, v1.y); h1.y = pack_h2(v1.z, v1.w);
    hp[t] = h0;
    hp[t + 256] = h1;
}

// ---------------- W prep: transpose + fp16. W[k][n] -> Wt[n][k] ----------------
template <int WHICH>
__global__ void __launch_bounds__(256) prep_w(const float* __restrict__ W) {
    __half* Wt = (WHICH == 0) ? g_w1t : g_w2t;
    __shared__ float tile[32][33];
    const int bx = blockIdx.x * 32;  // n block
    const int by = blockIdx.y * 32;  // k block
    const int tx = threadIdx.x & 31;
    const int ty = threadIdx.x >> 5;  // 0..7
#pragma unroll
    for (int j = 0; j < 32; j += 8)
        tile[ty + j][tx] = W[(size_t)(by + ty + j) * NTOT + bx + tx];
    __syncthreads();
#pragma unroll
    for (int j = 0; j < 32; j += 8) {
        const int n = bx + ty + j, k = by + tx;
        Wt[(size_t)n * KTOT + k] = __float2half_rn(tile[tx][ty + j]);
    }
}

// ---------------- HMMA GEMM ----------------
// CTA 128x128, 8 warps (2M x 4N), warp tile 64x32, K-chunk 32, 3-stage cp.async,
// 2 CTAs/SM. Smem/stage: A 128 x 80B + B 128 x 80B = 20480 B.
// PHASE 0: g_h_h = fp16(relu(xn @ W1)); PHASE 1: out = xnorm + dropout(h @ W2)
// with the threefry dropout mask computed inline in the epilogue.
#define APITCH 80
#define SM_B_OFF 10240
#define STAGE_BYTES 20480
#define GEMM_SMEM (3 * STAGE_BYTES)

template <int PHASE>
__global__ void __launch_bounds__(256, 2) gemm_mma(float* __restrict__ Cext) {
    extern __shared__ __align__(128) char smem[];
    const uint32_t sb = smem_u32(smem);
    const int tid = threadIdx.x;

    const __half* __restrict__ Ag = (PHASE == 0) ? g_xn_h : g_h_h;
    const __half* __restrict__ Bg = (PHASE == 0) ? g_w1t : g_w2t;
    const int m0 = blockIdx.y * 128;
    const int n0 = blockIdx.x * 128;

    // Loader: A/B each 128 rows x 4 16B-vecs per chunk; thread -> row tid/2, 2 vecs.
    const int lrow = tid >> 1;
    const int lv = (tid & 1) * 2;  // vec index 0 or 2
    const __half* agp = Ag + (size_t)(m0 + lrow) * KTOT + lv * 8;
    const __half* bgp = Bg + (size_t)(n0 + lrow) * KTOT + lv * 8;
    const uint32_t a_soff = (uint32_t)(lrow * APITCH + lv * 16);
    const uint32_t b_soff = (uint32_t)(SM_B_OFF + lrow * APITCH + lv * 16);

#define LOAD_STAGE(sidx, kc)                            \
    do {                                                \
        const uint32_t _st = sb + (sidx) * STAGE_BYTES; \
        cp16(_st + a_soff, agp + (kc));                 \
        cp16(_st + a_soff + 16, agp + (kc) + 8);        \
        cp16(_st + b_soff, bgp + (kc));                 \
        cp16(_st + b_soff + 16, bgp + (kc) + 8);        \
    } while (0)

    LOAD_STAGE(0, 0);
    asm volatile("cp.async.commit_group;" ::: "memory");
    LOAD_STAGE(1, 32);
    asm volatile("cp.async.commit_group;" ::: "memory");

    const int lane = tid & 31;
    const int wid = tid >> 5;
    const int wm = (wid >> 2) * 64;  // 0,64
    const int wn = (wid & 3) * 32;   // 0..96

    float acc[4][4][4];
#pragma unroll
    for (int mt = 0; mt < 4; mt++)
#pragma unroll
        for (int nt = 0; nt < 4; nt++)
#pragma unroll
            for (int j = 0; j < 4; j++) acc[mt][nt][j] = 0.0f;

    // ldmatrix bases (byte offsets within a stage).
    const uint32_t a_lm = (uint32_t)((wm + (lane & 15)) * APITCH + (lane >> 4) * 16);
    const uint32_t b_lm = (uint32_t)(SM_B_OFF +
                                     (wn + (lane & 7) + ((lane >> 4) << 3)) * APITCH +
                                     ((lane >> 3) & 1) * 16);

#pragma unroll 1
    for (int c = 0; c < KTOT / 32; c++) {
        asm volatile("cp.async.wait_group 1;" ::: "memory");
        __syncthreads();
        if (c + 2 < KTOT / 32) LOAD_STAGE((c + 2) % 3, (c + 2) * 32);
        asm volatile("cp.async.commit_group;" ::: "memory");

        const uint32_t st = sb + (c % 3) * STAGE_BYTES;
#pragma unroll
        for (int h = 0; h < 2; h++) {
            const uint32_t kb = h * 32;
            uint32_t a[4][4];
#pragma unroll
            for (int mt = 0; mt < 4; mt++) {
                const uint32_t addr = st + a_lm + mt * 16 * APITCH + kb;
                asm volatile(
                    "ldmatrix.sync.aligned.m8n8.x4.shared.b16 {%0,%1,%2,%3},[%4];"
                    : "=r"(a[mt][0]), "=r"(a[mt][1]), "=r"(a[mt][2]), "=r"(a[mt][3])
                    : "r"(addr));
            }
            uint32_t b[2][4];  // [pair][{nt0.b0, nt0.b1, nt1.b0, nt1.b1}]
#pragma unroll
            for (int p = 0; p < 2; p++) {
                const uint32_t addr = st + b_lm + p * 16 * APITCH + kb;
                asm volatile(
                    "ldmatrix.sync.aligned.m8n8.x4.shared.b16 {%0,%1,%2,%3},[%4];"
                    : "=r"(b[p][0]), "=r"(b[p][1]), "=r"(b[p][2]), "=r"(b[p][3])
                    : "r"(addr));
            }
#pragma unroll
            for (int nt = 0; nt < 4; nt++) {
                const uint32_t b0 = b[nt >> 1][(nt & 1) * 2];
                const uint32_t b1 = b[nt >> 1][(nt & 1) * 2 + 1];
#pragma unroll
                for (int mt = 0; mt < 4; mt++) mma16816(acc[mt][nt], a[mt], b0, b1);
            }
        }
    }

    // ---------------- epilogue ----------------
    const int rbase = m0 + wm + (lane >> 2);
    const int cbase = n0 + wn + (lane & 3) * 2;
    const float sc = 1.0f / 0.75f;
#pragma unroll
    for (int mt = 0; mt < 4; mt++) {
#pragma unroll
        for (int half = 0; half < 2; half++) {
            const int row = rbase + mt * 16 + half * 8;
            const size_t rowb = (size_t)row * NTOT;
#pragma unroll
            for (int nt = 0; nt < 4; nt++) {
                const int col = cbase + nt * 8;
                const float v0 = acc[mt][nt][2 * half];
                const float v1 = acc[mt][nt][2 * half + 1];
                if (PHASE == 0) {
                    *(uint32_t*)(g_h_h + rowb + col) =
                        pack_h2(fmaxf(v0, 0.0f), fmaxf(v1, 0.0f));
                } else {
                    const uint32_t i0 = (uint32_t)(rowb + col);
                    const float2 xr = *(const float2*)(g_xnorm + rowb + col);
                    float2 o;
                    o.x = xr.x + (tf_keep(i0) ? v0 * sc : 0.0f);
                    o.y = xr.y + (tf_keep(i0 + 1u) ? v1 * sc : 0.0f);
                    *(float2*)(Cext + rowb + col) = o;
                }
            }
        }
    }
#undef LOAD_STAGE
}

extern "C" void kernel_launch(void* const* d_in, const int* in_sizes, int n_in,
                              void* d_out, int out_size) {
    const float* inputs = (const float*)d_in[0];
    const float* W1 = (const float*)d_in[1];
    const float* W2 = (const float*)d_in[2];
    float* out = (float*)d_out;
    (void)in_sizes; (void)n_in; (void)out_size;

    cudaFuncSetAttribute(gemm_mma<0>, cudaFuncAttributeMaxDynamicSharedMemorySize, GEMM_SMEM);
    cudaFuncSetAttribute(gemm_mma<1>, cudaFuncAttributeMaxDynamicSharedMemorySize, GEMM_SMEM);

    dim3 tgrid(64, 64);
    prep_w<0><<<tgrid, 256>>>(W1);
    prep_w<1><<<tgrid, 256>>>(W2);
    ln_kernel<<<MTOT, 256>>>(inputs);

    dim3 grid(NTOT / 128, MTOT / 128);
    gemm_mma<0><<<grid, 256, GEMM_SMEM>>>(nullptr);
    gemm_mma<1><<<grid, 256, GEMM_SMEM>>>(out);
}